// round 13
// baseline (speedup 1.0000x reference)
#include <cuda_runtime.h>
#include <math.h>
#include <stdint.h>

#define Bq 8
#define Nq 2048
#define Cq 384
#define Hq 6
#define Dq 64
#define Mq (Bq * Nq)
#define QKVq (3 * Cq)
#define BHq (Bq * Hq)
#define LOG2E 1.4426950408889634f

__device__ float g_q[BHq * Nq * Dq];
__device__ float g_k[BHq * Nq * Dq];
__device__ float g_v[BHq * Nq * Dq];
__device__ float g_ctx[(size_t)Mq * Cq];

__device__ __forceinline__ uint32_t f2tf(float x) {
    uint32_t r;
    asm("cvt.rna.tf32.f32 %0, %1;" : "=r"(r) : "f"(x));
    return r;
}
__device__ __forceinline__ float tfv(float x) { return __uint_as_float(f2tf(x)); }
__device__ __forceinline__ float ex2(float x) {
    float r;
    asm("ex2.approx.f32 %0, %1;" : "=f"(r) : "f"(x));
    return r;
}
__device__ __forceinline__ void mma8(float* d, const uint32_t* a, const uint32_t* b) {
    asm volatile(
        "mma.sync.aligned.m16n8k8.row.col.f32.tf32.tf32.f32 "
        "{%0,%1,%2,%3},{%4,%5,%6,%7},{%8,%9},{%0,%1,%2,%3};"
        : "+f"(d[0]), "+f"(d[1]), "+f"(d[2]), "+f"(d[3])
        : "r"(a[0]), "r"(a[1]), "r"(a[2]), "r"(a[3]), "r"(b[0]), "r"(b[1]));
}
__device__ __forceinline__ void st_tf(float* d, float4 v) {
    d[0] = tfv(v.x); d[1] = tfv(v.y); d[2] = tfv(v.z); d[3] = tfv(v.w);
}

// ===========================================================================
// Shared GEMM core: single-tf32 both operands (unchanged from R8).
// ===========================================================================
#define GSTR 20
#define G_CH_FL (128 * GSTR)
#define G_SMEM_FLOATS (4 * G_CH_FL)

template <int KCHUNKS>
__device__ __forceinline__ void gemm_core(
    const float* __restrict__ x, const float* __restrict__ w,
    int m0, int j0, int K, float* smg, float acc[2][8][4])
{
    float* Xs = smg;
    float* Ws = smg + 2 * G_CH_FL;

    const int tid = threadIdx.x, lane = tid & 31, wp = tid >> 5;
    const int g = lane >> 2, t = lane & 3;
    const int wm = wp & 3, wn = wp >> 2;

#pragma unroll
    for (int a = 0; a < 2; a++)
#pragma unroll
        for (int b = 0; b < 8; b++)
#pragma unroll
            for (int c = 0; c < 4; c++) acc[a][b][c] = 0.f;

    float4 xr[2], wr[2];
#pragma unroll
    for (int i = 0; i < 2; i++) {
        int f = tid + i * 256;
        int row = f >> 2, c4 = (f & 3) * 4;
        xr[i] = *(const float4*)&x[(size_t)(m0 + row) * K + c4];
        wr[i] = *(const float4*)&w[(size_t)(j0 + row) * K + c4];
    }
#pragma unroll
    for (int i = 0; i < 2; i++) {
        int f = tid + i * 256;
        int row = f >> 2, c4 = (f & 3) * 4;
        st_tf(&Xs[row * GSTR + c4], xr[i]);
        st_tf(&Ws[row * GSTR + c4], wr[i]);
    }

    for (int ch = 0; ch < KCHUNKS; ch++) {
        if (ch < KCHUNKS - 1) {
            int k0 = (ch + 1) * 16;
#pragma unroll
            for (int i = 0; i < 2; i++) {
                int f = tid + i * 256;
                int row = f >> 2, c4 = (f & 3) * 4;
                xr[i] = *(const float4*)&x[(size_t)(m0 + row) * K + k0 + c4];
                wr[i] = *(const float4*)&w[(size_t)(j0 + row) * K + k0 + c4];
            }
        }
        __syncthreads();
        const float* Xc = Xs + (ch & 1) * G_CH_FL;
        const float* Wc = Ws + (ch & 1) * G_CH_FL;

#pragma unroll
        for (int ks = 0; ks < 2; ks++) {
            uint32_t af[2][4];
#pragma unroll
            for (int mt = 0; mt < 2; mt++) {
                int r = wm * 32 + mt * 16;
                af[mt][0] = __float_as_uint(Xc[(r + g) * GSTR + ks * 8 + t]);
                af[mt][1] = __float_as_uint(Xc[(r + g + 8) * GSTR + ks * 8 + t]);
                af[mt][2] = __float_as_uint(Xc[(r + g) * GSTR + ks * 8 + t + 4]);
                af[mt][3] = __float_as_uint(Xc[(r + g + 8) * GSTR + ks * 8 + t + 4]);
            }
#pragma unroll
            for (int nt = 0; nt < 8; nt++) {
                int c = wn * 64 + nt * 8;
                uint32_t bw[2] = {
                    __float_as_uint(Wc[(c + g) * GSTR + ks * 8 + t]),
                    __float_as_uint(Wc[(c + g) * GSTR + ks * 8 + t + 4])};
                mma8(acc[0][nt], af[0], bw);
                mma8(acc[1][nt], af[1], bw);
            }
        }
        if (ch < KCHUNKS - 1) {
            float* Xd = Xs + ((ch + 1) & 1) * G_CH_FL;
            float* Wd = Ws + ((ch + 1) & 1) * G_CH_FL;
#pragma unroll
            for (int i = 0; i < 2; i++) {
                int f = tid + i * 256;
                int row = f >> 2, c4 = (f & 3) * 4;
                st_tf(&Xd[row * GSTR + c4], xr[i]);
                st_tf(&Wd[row * GSTR + c4], wr[i]);
            }
        }
    }
}

__global__ __launch_bounds__(256, 2) void qkv_gemm_kernel(
    const float* __restrict__ x, const float* __restrict__ wq)
{
    extern __shared__ float smg[];
    float acc[2][8][4];
    const int m0 = blockIdx.y * 128, j0 = blockIdx.x * 128;
    gemm_core<24>(x, wq, m0, j0, Cq, smg, acc);

    const int tid = threadIdx.x, lane = tid & 31, wp = tid >> 5;
    const int g = lane >> 2, t = lane & 3;
    const int wm = wp & 3, wn = wp >> 2;

#pragma unroll
    for (int nt = 0; nt < 8; nt++) {
        int j = j0 + wn * 64 + nt * 8 + 2 * t;
        int s = j / Cq;
        int jj = j - s * Cq;
        int h = jj >> 6, d = jj & 63;
        float* dst = (s == 0) ? g_q : ((s == 1) ? g_k : g_v);
#pragma unroll
        for (int mt = 0; mt < 2; mt++) {
            int m = m0 + wm * 32 + mt * 16 + g;
            int bb = m >> 11, nn = m & (Nq - 1);
            *(float2*)&dst[(((size_t)bb * Hq + h) * Nq + nn) * Dq + d] =
                make_float2(acc[mt][nt][0], acc[mt][nt][1]);
            m += 8; bb = m >> 11; nn = m & (Nq - 1);
            *(float2*)&dst[(((size_t)bb * Hq + h) * Nq + nn) * Dq + d] =
                make_float2(acc[mt][nt][2], acc[mt][nt][3]);
        }
    }
}

__global__ __launch_bounds__(256, 2) void proj_gemm_kernel(
    const float* __restrict__ w, const float* __restrict__ bias,
    float* __restrict__ out)
{
    extern __shared__ float smg[];
    float acc[2][8][4];
    const int m0 = blockIdx.y * 128, j0 = blockIdx.x * 128;
    gemm_core<24>(g_ctx, w, m0, j0, Cq, smg, acc);

    const int tid = threadIdx.x, lane = tid & 31, wp = tid >> 5;
    const int g = lane >> 2, t = lane & 3;
    const int wm = wp & 3, wn = wp >> 2;

#pragma unroll
    for (int nt = 0; nt < 8; nt++) {
        int j = j0 + wn * 64 + nt * 8 + 2 * t;
        float2 bv = *(const float2*)&bias[j];
#pragma unroll
        for (int mt = 0; mt < 2; mt++) {
            int m = m0 + wm * 32 + mt * 16 + g;
            *(float2*)&out[(size_t)m * Cq + j] =
                make_float2(acc[mt][nt][0] + bv.x, acc[mt][nt][1] + bv.y);
            *(float2*)&out[(size_t)(m + 8) * Cq + j] =
                make_float2(acc[mt][nt][2] + bv.x, acc[mt][nt][3] + bv.y);
        }
    }
}

// ===========================================================================
// Kernel 2: fused attention v4.
// CTA = (b,h) x 256 rows; 256 threads (8 warps x 32 rows = 2 m16 tiles each).
// B-fragments (K and V) loaded once per warp feed BOTH m-tiles -> LDS halved.
// Q A-fragments from gmem; K/V double-buffered in smem (R5 strides, no permute).
// ===========================================================================
#define KSTRD 68
#define VSTRD 72
#define A_KB_FL (64 * KSTRD)
#define A_VB_FL (64 * VSTRD)
#define A_SMEM_FLOATS (2 * A_KB_FL + 2 * A_VB_FL)   // 17920 fl = 71680 B

__global__ __launch_bounds__(256, 1) void attn_kernel(float* __restrict__ attnp)
{
    extern __shared__ float sma[];
    float* Kb = sma;                  // [2][64][KSTRD]
    float* Vb = sma + 2 * A_KB_FL;    // [2][64][VSTRD]

    const int tid = threadIdx.x, lane = tid & 31, w = tid >> 5;
    const int g = lane >> 2, t = lane & 3;
    const int bh = blockIdx.y, q0 = blockIdx.x * 256;
    const int b = bh / Hq, h = bh - b * Hq;

    const float* qptr = g_q + (size_t)bh * Nq * Dq;
    const float* kptr = g_k + (size_t)bh * Nq * Dq;
    const float* vptr = g_v + (size_t)bh * Nq * Dq;

    // ---- Q A-fragments from gmem: warp w owns rows w*32 .. w*32+31 ----
    const float qsc = 0.125f * LOG2E;
    uint32_t Ah[2][8][4];
#pragma unroll
    for (int mt = 0; mt < 2; mt++) {
        const float* q0p = qptr + (size_t)(q0 + w * 32 + mt * 16 + g) * Dq;
        const float* q1p = q0p + 8 * Dq;
#pragma unroll
        for (int ks = 0; ks < 8; ks++) {
            int dd = ks * 8 + t;
            Ah[mt][ks][0] = f2tf(q0p[dd] * qsc);
            Ah[mt][ks][1] = f2tf(q1p[dd] * qsc);
            Ah[mt][ks][2] = f2tf(q0p[dd + 4] * qsc);
            Ah[mt][ks][3] = f2tf(q1p[dd + 4] * qsc);
        }
    }

    // loader mapping: 1024 float4 per matrix per chunk, 4 per thread
    const int lkey = tid >> 4, ld4 = (tid & 15) * 4;   // keys 0..15 (+16 stride), d 0..60

    // ================= pass 1: row sums =================
    float l0[2] = {0.f, 0.f}, l1[2] = {0.f, 0.f};
    {
        float4 kr[4];
#pragma unroll
        for (int i = 0; i < 4; i++) {
            int key = lkey + i * 16;
            kr[i] = *(const float4*)&kptr[(size_t)key * Dq + ld4];
        }
#pragma unroll
        for (int i = 0; i < 4; i++)
            st_tf(&Kb[(lkey + i * 16) * KSTRD + ld4], kr[i]);

        for (int sc = 0; sc < 32; sc++) {
            if (sc < 31) {
                const float* kp = kptr + (size_t)(sc + 1) * 64 * Dq;
#pragma unroll
                for (int i = 0; i < 4; i++)
                    kr[i] = *(const float4*)&kp[(size_t)(lkey + i * 16) * Dq + ld4];
            }
            __syncthreads();
            const float* kc = Kb + (sc & 1) * A_KB_FL;
#pragma unroll
            for (int nt = 0; nt < 8; nt++) {
                float a4[2][4] = {{0.f, 0.f, 0.f, 0.f}, {0.f, 0.f, 0.f, 0.f}};
#pragma unroll
                for (int ks = 0; ks < 8; ks++) {
                    uint32_t bb[2] = {
                        __float_as_uint(kc[(nt * 8 + g) * KSTRD + ks * 8 + t]),
                        __float_as_uint(kc[(nt * 8 + g) * KSTRD + ks * 8 + t + 4])};
                    mma8(a4[0], Ah[0][ks], bb);
                    mma8(a4[1], Ah[1][ks], bb);
                }
#pragma unroll
                for (int mt = 0; mt < 2; mt++) {
                    l0[mt] += ex2(a4[mt][0]) + ex2(a4[mt][1]);
                    l1[mt] += ex2(a4[mt][2]) + ex2(a4[mt][3]);
                }
            }
            if (sc < 31) {
                float* kd = Kb + ((sc + 1) & 1) * A_KB_FL;
#pragma unroll
                for (int i = 0; i < 4; i++)
                    st_tf(&kd[(lkey + i * 16) * KSTRD + ld4], kr[i]);
            }
        }
    }
    float rinv0[2], rinv1[2];
#pragma unroll
    for (int mt = 0; mt < 2; mt++) {
        float a = l0[mt], c = l1[mt];
        a += __shfl_xor_sync(0xffffffffu, a, 1);
        a += __shfl_xor_sync(0xffffffffu, a, 2);
        c += __shfl_xor_sync(0xffffffffu, c, 1);
        c += __shfl_xor_sync(0xffffffffu, c, 2);
        rinv0[mt] = 1.f / a;
        rinv1[mt] = 1.f / c;
    }

    // ================= pass 2: attn + PV =================
    float vacc[2][8][4];
#pragma unroll
    for (int mt = 0; mt < 2; mt++)
#pragma unroll
        for (int d = 0; d < 8; d++)
#pragma unroll
            for (int j = 0; j < 4; j++) vacc[mt][d][j] = 0.f;

    float* ap[2] = {
        attnp ? attnp + ((size_t)bh * Nq + (q0 + w * 32 + g)) * (size_t)Nq : (float*)0,
        attnp ? attnp + ((size_t)bh * Nq + (q0 + w * 32 + 16 + g)) * (size_t)Nq : (float*)0};

    {
        float4 kr[4], vr[4];
#pragma unroll
        for (int i = 0; i < 4; i++) {
            int key = lkey + i * 16;
            kr[i] = *(const float4*)&kptr[(size_t)key * Dq + ld4];
            vr[i] = *(const float4*)&vptr[(size_t)key * Dq + ld4];
        }
        __syncthreads();   // pass-1 reads complete before overwrite
#pragma unroll
        for (int i = 0; i < 4; i++) {
            st_tf(&Kb[(lkey + i * 16) * KSTRD + ld4], kr[i]);
            st_tf(&Vb[(lkey + i * 16) * VSTRD + ld4], vr[i]);
        }

        const int L0 = g * 4 + (t >> 1);
        const int L1 = L0 + 2;
        const bool odd = (t & 1);

        for (int sc = 0; sc < 32; sc++) {
            if (sc < 31) {
                const float* kp = kptr + (size_t)(sc + 1) * 64 * Dq;
                const float* vp = vptr + (size_t)(sc + 1) * 64 * Dq;
#pragma unroll
                for (int i = 0; i < 4; i++) {
                    kr[i] = *(const float4*)&kp[(size_t)(lkey + i * 16) * Dq + ld4];
                    vr[i] = *(const float4*)&vp[(size_t)(lkey + i * 16) * Dq + ld4];
                }
            }
            __syncthreads();
            const float* kc = Kb + (sc & 1) * A_KB_FL;
            const float* vc = Vb + (sc & 1) * A_VB_FL;

#pragma unroll
            for (int nt = 0; nt < 8; nt++) {
                float a4[2][4] = {{0.f, 0.f, 0.f, 0.f}, {0.f, 0.f, 0.f, 0.f}};
#pragma unroll
                for (int ks = 0; ks < 8; ks++) {
                    uint32_t bb[2] = {
                        __float_as_uint(kc[(nt * 8 + g) * KSTRD + ks * 8 + t]),
                        __float_as_uint(kc[(nt * 8 + g) * KSTRD + ks * 8 + t + 4])};
                    mma8(a4[0], Ah[0][ks], bb);
                    mma8(a4[1], Ah[1][ks], bb);
                }
                int col = sc * 64 + nt * 8 + 2 * t;
                uint32_t af[2][4];
#pragma unroll
                for (int mt = 0; mt < 2; mt++) {
                    float p0 = ex2(a4[mt][0]) * rinv0[mt];
                    float p1 = ex2(a4[mt][1]) * rinv0[mt];
                    float p2 = ex2(a4[mt][2]) * rinv1[mt];
                    float p3 = ex2(a4[mt][3]) * rinv1[mt];
                    if (ap[mt]) {
                        *(float2*)&ap[mt][col] = make_float2(p0, p1);
                        *(float2*)&ap[mt][8 * (size_t)Nq + col] = make_float2(p2, p3);
                    }
                    float x0 = __shfl_sync(0xffffffffu, p0, L0);
                    float y0 = __shfl_sync(0xffffffffu, p1, L0);
                    float x1 = __shfl_sync(0xffffffffu, p2, L0);
                    float y1 = __shfl_sync(0xffffffffu, p3, L0);
                    float x2 = __shfl_sync(0xffffffffu, p0, L1);
                    float y2 = __shfl_sync(0xffffffffu, p1, L1);
                    float x3 = __shfl_sync(0xffffffffu, p2, L1);
                    float y3 = __shfl_sync(0xffffffffu, p3, L1);
                    af[mt][0] = f2tf(odd ? y0 : x0);
                    af[mt][1] = f2tf(odd ? y1 : x1);
                    af[mt][2] = f2tf(odd ? y2 : x2);
                    af[mt][3] = f2tf(odd ? y3 : x3);
                }
#pragma unroll
                for (int nt2 = 0; nt2 < 8; nt2++) {
                    uint32_t bb2[2] = {
                        __float_as_uint(vc[(nt * 8 + t) * VSTRD + nt2 * 8 + g]),
                        __float_as_uint(vc[(nt * 8 + t + 4) * VSTRD + nt2 * 8 + g])};
                    mma8(vacc[0][nt2], af[0], bb2);
                    mma8(vacc[1][nt2], af[1], bb2);
                }
            }
            if (sc < 31) {
                float* kd = Kb + ((sc + 1) & 1) * A_KB_FL;
                float* vd = Vb + ((sc + 1) & 1) * A_VB_FL;
#pragma unroll
                for (int i = 0; i < 4; i++) {
                    st_tf(&kd[(lkey + i * 16) * KSTRD + ld4], kr[i]);
                    st_tf(&vd[(lkey + i * 16) * VSTRD + ld4], vr[i]);
                }
            }
        }
    }

    // write ctx
#pragma unroll
    for (int mt = 0; mt < 2; mt++) {
        size_t tok0 = (size_t)b * Nq + (q0 + w * 32 + mt * 16 + g);
        size_t tok1 = tok0 + 8;
#pragma unroll
        for (int nt2 = 0; nt2 < 8; nt2++) {
            int dc = h * Dq + nt2 * 8 + 2 * t;
            *(float2*)&g_ctx[tok0 * Cq + dc] =
                make_float2(vacc[mt][nt2][0], vacc[mt][nt2][1]);
            *(float2*)&g_ctx[tok1 * Cq + dc] =
                make_float2(vacc[mt][nt2][2], vacc[mt][nt2][3]);
        }
    }
}

// ===========================================================================
extern "C" void kernel_launch(void* const* d_in, const int* in_sizes, int n_in,
                              void* d_out, int out_size)
{
    const float* x      = (const float*)d_in[0];
    const float* w_qkv  = (const float*)d_in[1];
    const float* w_proj = (const float*)d_in[2];
    const float* b_proj = (const float*)d_in[3];

    const size_t out_elems  = (size_t)Mq * Cq;
    const size_t attn_elems = (size_t)BHq * Nq * (size_t)Nq;

    float* outp  = nullptr;
    float* attnp = nullptr;
    if ((size_t)out_size >= out_elems + attn_elems) {
        outp  = (float*)d_out;
        attnp = (float*)d_out + out_elems;
    } else if ((size_t)out_size == attn_elems) {
        attnp = (float*)d_out;
    } else {
        outp = (float*)d_out;
    }

    static const int gsm_bytes = G_SMEM_FLOATS * 4;
    cudaFuncSetAttribute(qkv_gemm_kernel, cudaFuncAttributeMaxDynamicSharedMemorySize,
                         gsm_bytes);
    cudaFuncSetAttribute(proj_gemm_kernel, cudaFuncAttributeMaxDynamicSharedMemorySize,
                         gsm_bytes);

    qkv_gemm_kernel<<<dim3(QKVq / 128, Mq / 128), 256, gsm_bytes>>>(x, w_qkv);

    static const int asm_bytes = A_SMEM_FLOATS * 4;   // 71680
    cudaFuncSetAttribute(attn_kernel, cudaFuncAttributeMaxDynamicSharedMemorySize,
                         asm_bytes);
    attn_kernel<<<dim3(Nq / 256, BHq), 256, asm_bytes>>>(attnp);

    if (outp) {
        proj_gemm_kernel<<<dim3(Cq / 128, Mq / 128), 256, gsm_bytes>>>(w_proj, b_proj, outp);
    }
}

// round 14
// speedup vs baseline: 1.0002x; 1.0002x over previous
#include <cuda_runtime.h>
#include <math.h>
#include <stdint.h>

#define Bq 8
#define Nq 2048
#define Cq 384
#define Hq 6
#define Dq 64
#define Mq (Bq * Nq)
#define QKVq (3 * Cq)
#define BHq (Bq * Hq)
#define LOG2E 1.4426950408889634f

__device__ float g_q[BHq * Nq * Dq];
__device__ float g_k[BHq * Nq * Dq];
__device__ float g_v[BHq * Nq * Dq];
__device__ float g_ctx[(size_t)Mq * Cq];

__device__ __forceinline__ uint32_t f2tf(float x) {
    uint32_t r;
    asm("cvt.rna.tf32.f32 %0, %1;" : "=r"(r) : "f"(x));
    return r;
}
__device__ __forceinline__ float tfv(float x) { return __uint_as_float(f2tf(x)); }
__device__ __forceinline__ float ex2(float x) {
    float r;
    asm("ex2.approx.f32 %0, %1;" : "=f"(r) : "f"(x));
    return r;
}
__device__ __forceinline__ void mma8(float* d, const uint32_t* a, const uint32_t* b) {
    asm volatile(
        "mma.sync.aligned.m16n8k8.row.col.f32.tf32.tf32.f32 "
        "{%0,%1,%2,%3},{%4,%5,%6,%7},{%8,%9},{%0,%1,%2,%3};"
        : "+f"(d[0]), "+f"(d[1]), "+f"(d[2]), "+f"(d[3])
        : "r"(a[0]), "r"(a[1]), "r"(a[2]), "r"(a[3]), "r"(b[0]), "r"(b[1]));
}
__device__ __forceinline__ void st_tf(float* d, float4 v) {
    d[0] = tfv(v.x); d[1] = tfv(v.y); d[2] = tfv(v.z); d[3] = tfv(v.w);
}

// ===========================================================================
// Shared GEMM core: single-tf32 both operands (unchanged from R8).
// ===========================================================================
#define GSTR 20
#define G_CH_FL (128 * GSTR)
#define G_SMEM_FLOATS (4 * G_CH_FL)

template <int KCHUNKS>
__device__ __forceinline__ void gemm_core(
    const float* __restrict__ x, const float* __restrict__ w,
    int m0, int j0, int K, float* smg, float acc[2][8][4])
{
    float* Xs = smg;
    float* Ws = smg + 2 * G_CH_FL;

    const int tid = threadIdx.x, lane = tid & 31, wp = tid >> 5;
    const int g = lane >> 2, t = lane & 3;
    const int wm = wp & 3, wn = wp >> 2;

#pragma unroll
    for (int a = 0; a < 2; a++)
#pragma unroll
        for (int b = 0; b < 8; b++)
#pragma unroll
            for (int c = 0; c < 4; c++) acc[a][b][c] = 0.f;

    float4 xr[2], wr[2];
#pragma unroll
    for (int i = 0; i < 2; i++) {
        int f = tid + i * 256;
        int row = f >> 2, c4 = (f & 3) * 4;
        xr[i] = *(const float4*)&x[(size_t)(m0 + row) * K + c4];
        wr[i] = *(const float4*)&w[(size_t)(j0 + row) * K + c4];
    }
#pragma unroll
    for (int i = 0; i < 2; i++) {
        int f = tid + i * 256;
        int row = f >> 2, c4 = (f & 3) * 4;
        st_tf(&Xs[row * GSTR + c4], xr[i]);
        st_tf(&Ws[row * GSTR + c4], wr[i]);
    }

    for (int ch = 0; ch < KCHUNKS; ch++) {
        if (ch < KCHUNKS - 1) {
            int k0 = (ch + 1) * 16;
#pragma unroll
            for (int i = 0; i < 2; i++) {
                int f = tid + i * 256;
                int row = f >> 2, c4 = (f & 3) * 4;
                xr[i] = *(const float4*)&x[(size_t)(m0 + row) * K + k0 + c4];
                wr[i] = *(const float4*)&w[(size_t)(j0 + row) * K + k0 + c4];
            }
        }
        __syncthreads();
        const float* Xc = Xs + (ch & 1) * G_CH_FL;
        const float* Wc = Ws + (ch & 1) * G_CH_FL;

#pragma unroll
        for (int ks = 0; ks < 2; ks++) {
            uint32_t af[2][4];
#pragma unroll
            for (int mt = 0; mt < 2; mt++) {
                int r = wm * 32 + mt * 16;
                af[mt][0] = __float_as_uint(Xc[(r + g) * GSTR + ks * 8 + t]);
                af[mt][1] = __float_as_uint(Xc[(r + g + 8) * GSTR + ks * 8 + t]);
                af[mt][2] = __float_as_uint(Xc[(r + g) * GSTR + ks * 8 + t + 4]);
                af[mt][3] = __float_as_uint(Xc[(r + g + 8) * GSTR + ks * 8 + t + 4]);
            }
#pragma unroll
            for (int nt = 0; nt < 8; nt++) {
                int c = wn * 64 + nt * 8;
                uint32_t bw[2] = {
                    __float_as_uint(Wc[(c + g) * GSTR + ks * 8 + t]),
                    __float_as_uint(Wc[(c + g) * GSTR + ks * 8 + t + 4])};
                mma8(acc[0][nt], af[0], bw);
                mma8(acc[1][nt], af[1], bw);
            }
        }
        if (ch < KCHUNKS - 1) {
            float* Xd = Xs + ((ch + 1) & 1) * G_CH_FL;
            float* Wd = Ws + ((ch + 1) & 1) * G_CH_FL;
#pragma unroll
            for (int i = 0; i < 2; i++) {
                int f = tid + i * 256;
                int row = f >> 2, c4 = (f & 3) * 4;
                st_tf(&Xd[row * GSTR + c4], xr[i]);
                st_tf(&Wd[row * GSTR + c4], wr[i]);
            }
        }
    }
}

__global__ __launch_bounds__(256, 2) void qkv_gemm_kernel(
    const float* __restrict__ x, const float* __restrict__ wq)
{
    extern __shared__ float smg[];
    float acc[2][8][4];
    const int m0 = blockIdx.y * 128, j0 = blockIdx.x * 128;
    gemm_core<24>(x, wq, m0, j0, Cq, smg, acc);

    const int tid = threadIdx.x, lane = tid & 31, wp = tid >> 5;
    const int g = lane >> 2, t = lane & 3;
    const int wm = wp & 3, wn = wp >> 2;

#pragma unroll
    for (int nt = 0; nt < 8; nt++) {
        int j = j0 + wn * 64 + nt * 8 + 2 * t;
        int s = j / Cq;
        int jj = j - s * Cq;
        int h = jj >> 6, d = jj & 63;
        float* dst = (s == 0) ? g_q : ((s == 1) ? g_k : g_v);
#pragma unroll
        for (int mt = 0; mt < 2; mt++) {
            int m = m0 + wm * 32 + mt * 16 + g;
            int bb = m >> 11, nn = m & (Nq - 1);
            *(float2*)&dst[(((size_t)bb * Hq + h) * Nq + nn) * Dq + d] =
                make_float2(acc[mt][nt][0], acc[mt][nt][1]);
            m += 8; bb = m >> 11; nn = m & (Nq - 1);
            *(float2*)&dst[(((size_t)bb * Hq + h) * Nq + nn) * Dq + d] =
                make_float2(acc[mt][nt][2], acc[mt][nt][3]);
        }
    }
}

__global__ __launch_bounds__(256, 2) void proj_gemm_kernel(
    const float* __restrict__ w, const float* __restrict__ bias,
    float* __restrict__ out)
{
    extern __shared__ float smg[];
    float acc[2][8][4];
    const int m0 = blockIdx.y * 128, j0 = blockIdx.x * 128;
    gemm_core<24>(g_ctx, w, m0, j0, Cq, smg, acc);

    const int tid = threadIdx.x, lane = tid & 31, wp = tid >> 5;
    const int g = lane >> 2, t = lane & 3;
    const int wm = wp & 3, wn = wp >> 2;

#pragma unroll
    for (int nt = 0; nt < 8; nt++) {
        int j = j0 + wn * 64 + nt * 8 + 2 * t;
        float2 bv = *(const float2*)&bias[j];
#pragma unroll
        for (int mt = 0; mt < 2; mt++) {
            int m = m0 + wm * 32 + mt * 16 + g;
            *(float2*)&out[(size_t)m * Cq + j] =
                make_float2(acc[mt][nt][0] + bv.x, acc[mt][nt][1] + bv.y);
            *(float2*)&out[(size_t)(m + 8) * Cq + j] =
                make_float2(acc[mt][nt][2] + bv.x, acc[mt][nt][3] + bv.y);
        }
    }
}

// ===========================================================================
// Kernel 2: fused attention v4.
// CTA = (b,h) x 256 rows; 256 threads (8 warps x 32 rows = 2 m16 tiles each).
// B-fragments (K and V) loaded once per warp feed BOTH m-tiles -> LDS halved.
// Q A-fragments from gmem; K/V double-buffered in smem (R5 strides, no permute).
// ===========================================================================
#define KSTRD 68
#define VSTRD 72
#define A_KB_FL (64 * KSTRD)
#define A_VB_FL (64 * VSTRD)
#define A_SMEM_FLOATS (2 * A_KB_FL + 2 * A_VB_FL)   // 17920 fl = 71680 B

__global__ __launch_bounds__(256, 1) void attn_kernel(float* __restrict__ attnp)
{
    extern __shared__ float sma[];
    float* Kb = sma;                  // [2][64][KSTRD]
    float* Vb = sma + 2 * A_KB_FL;    // [2][64][VSTRD]

    const int tid = threadIdx.x, lane = tid & 31, w = tid >> 5;
    const int g = lane >> 2, t = lane & 3;
    const int bh = blockIdx.y, q0 = blockIdx.x * 256;
    const int b = bh / Hq, h = bh - b * Hq;

    const float* qptr = g_q + (size_t)bh * Nq * Dq;
    const float* kptr = g_k + (size_t)bh * Nq * Dq;
    const float* vptr = g_v + (size_t)bh * Nq * Dq;

    // ---- Q A-fragments from gmem: warp w owns rows w*32 .. w*32+31 ----
    const float qsc = 0.125f * LOG2E;
    uint32_t Ah[2][8][4];
#pragma unroll
    for (int mt = 0; mt < 2; mt++) {
        const float* q0p = qptr + (size_t)(q0 + w * 32 + mt * 16 + g) * Dq;
        const float* q1p = q0p + 8 * Dq;
#pragma unroll
        for (int ks = 0; ks < 8; ks++) {
            int dd = ks * 8 + t;
            Ah[mt][ks][0] = f2tf(q0p[dd] * qsc);
            Ah[mt][ks][1] = f2tf(q1p[dd] * qsc);
            Ah[mt][ks][2] = f2tf(q0p[dd + 4] * qsc);
            Ah[mt][ks][3] = f2tf(q1p[dd + 4] * qsc);
        }
    }

    // loader mapping: 1024 float4 per matrix per chunk, 4 per thread
    const int lkey = tid >> 4, ld4 = (tid & 15) * 4;   // keys 0..15 (+16 stride), d 0..60

    // ================= pass 1: row sums =================
    float l0[2] = {0.f, 0.f}, l1[2] = {0.f, 0.f};
    {
        float4 kr[4];
#pragma unroll
        for (int i = 0; i < 4; i++) {
            int key = lkey + i * 16;
            kr[i] = *(const float4*)&kptr[(size_t)key * Dq + ld4];
        }
#pragma unroll
        for (int i = 0; i < 4; i++)
            st_tf(&Kb[(lkey + i * 16) * KSTRD + ld4], kr[i]);

        for (int sc = 0; sc < 32; sc++) {
            if (sc < 31) {
                const float* kp = kptr + (size_t)(sc + 1) * 64 * Dq;
#pragma unroll
                for (int i = 0; i < 4; i++)
                    kr[i] = *(const float4*)&kp[(size_t)(lkey + i * 16) * Dq + ld4];
            }
            __syncthreads();
            const float* kc = Kb + (sc & 1) * A_KB_FL;
#pragma unroll
            for (int nt = 0; nt < 8; nt++) {
                float a4[2][4] = {{0.f, 0.f, 0.f, 0.f}, {0.f, 0.f, 0.f, 0.f}};
#pragma unroll
                for (int ks = 0; ks < 8; ks++) {
                    uint32_t bb[2] = {
                        __float_as_uint(kc[(nt * 8 + g) * KSTRD + ks * 8 + t]),
                        __float_as_uint(kc[(nt * 8 + g) * KSTRD + ks * 8 + t + 4])};
                    mma8(a4[0], Ah[0][ks], bb);
                    mma8(a4[1], Ah[1][ks], bb);
                }
#pragma unroll
                for (int mt = 0; mt < 2; mt++) {
                    l0[mt] += ex2(a4[mt][0]) + ex2(a4[mt][1]);
                    l1[mt] += ex2(a4[mt][2]) + ex2(a4[mt][3]);
                }
            }
            if (sc < 31) {
                float* kd = Kb + ((sc + 1) & 1) * A_KB_FL;
#pragma unroll
                for (int i = 0; i < 4; i++)
                    st_tf(&kd[(lkey + i * 16) * KSTRD + ld4], kr[i]);
            }
        }
    }
    float rinv0[2], rinv1[2];
#pragma unroll
    for (int mt = 0; mt < 2; mt++) {
        float a = l0[mt], c = l1[mt];
        a += __shfl_xor_sync(0xffffffffu, a, 1);
        a += __shfl_xor_sync(0xffffffffu, a, 2);
        c += __shfl_xor_sync(0xffffffffu, c, 1);
        c += __shfl_xor_sync(0xffffffffu, c, 2);
        rinv0[mt] = 1.f / a;
        rinv1[mt] = 1.f / c;
    }

    // ================= pass 2: attn + PV =================
    float vacc[2][8][4];
#pragma unroll
    for (int mt = 0; mt < 2; mt++)
#pragma unroll
        for (int d = 0; d < 8; d++)
#pragma unroll
            for (int j = 0; j < 4; j++) vacc[mt][d][j] = 0.f;

    float* ap[2] = {
        attnp ? attnp + ((size_t)bh * Nq + (q0 + w * 32 + g)) * (size_t)Nq : (float*)0,
        attnp ? attnp + ((size_t)bh * Nq + (q0 + w * 32 + 16 + g)) * (size_t)Nq : (float*)0};

    {
        float4 kr[4], vr[4];
#pragma unroll
        for (int i = 0; i < 4; i++) {
            int key = lkey + i * 16;
            kr[i] = *(const float4*)&kptr[(size_t)key * Dq + ld4];
            vr[i] = *(const float4*)&vptr[(size_t)key * Dq + ld4];
        }
        __syncthreads();   // pass-1 reads complete before overwrite
#pragma unroll
        for (int i = 0; i < 4; i++) {
            st_tf(&Kb[(lkey + i * 16) * KSTRD + ld4], kr[i]);
            st_tf(&Vb[(lkey + i * 16) * VSTRD + ld4], vr[i]);
        }

        const int L0 = g * 4 + (t >> 1);
        const int L1 = L0 + 2;
        const bool odd = (t & 1);

        for (int sc = 0; sc < 32; sc++) {
            if (sc < 31) {
                const float* kp = kptr + (size_t)(sc + 1) * 64 * Dq;
                const float* vp = vptr + (size_t)(sc + 1) * 64 * Dq;
#pragma unroll
                for (int i = 0; i < 4; i++) {
                    kr[i] = *(const float4*)&kp[(size_t)(lkey + i * 16) * Dq + ld4];
                    vr[i] = *(const float4*)&vp[(size_t)(lkey + i * 16) * Dq + ld4];
                }
            }
            __syncthreads();
            const float* kc = Kb + (sc & 1) * A_KB_FL;
            const float* vc = Vb + (sc & 1) * A_VB_FL;

#pragma unroll
            for (int nt = 0; nt < 8; nt++) {
                float a4[2][4] = {{0.f, 0.f, 0.f, 0.f}, {0.f, 0.f, 0.f, 0.f}};
#pragma unroll
                for (int ks = 0; ks < 8; ks++) {
                    uint32_t bb[2] = {
                        __float_as_uint(kc[(nt * 8 + g) * KSTRD + ks * 8 + t]),
                        __float_as_uint(kc[(nt * 8 + g) * KSTRD + ks * 8 + t + 4])};
                    mma8(a4[0], Ah[0][ks], bb);
                    mma8(a4[1], Ah[1][ks], bb);
                }
                int col = sc * 64 + nt * 8 + 2 * t;
                uint32_t af[2][4];
#pragma unroll
                for (int mt = 0; mt < 2; mt++) {
                    float p0 = ex2(a4[mt][0]) * rinv0[mt];
                    float p1 = ex2(a4[mt][1]) * rinv0[mt];
                    float p2 = ex2(a4[mt][2]) * rinv1[mt];
                    float p3 = ex2(a4[mt][3]) * rinv1[mt];
                    if (ap[mt]) {
                        *(float2*)&ap[mt][col] = make_float2(p0, p1);
                        *(float2*)&ap[mt][8 * (size_t)Nq + col] = make_float2(p2, p3);
                    }
                    float x0 = __shfl_sync(0xffffffffu, p0, L0);
                    float y0 = __shfl_sync(0xffffffffu, p1, L0);
                    float x1 = __shfl_sync(0xffffffffu, p2, L0);
                    float y1 = __shfl_sync(0xffffffffu, p3, L0);
                    float x2 = __shfl_sync(0xffffffffu, p0, L1);
                    float y2 = __shfl_sync(0xffffffffu, p1, L1);
                    float x3 = __shfl_sync(0xffffffffu, p2, L1);
                    float y3 = __shfl_sync(0xffffffffu, p3, L1);
                    af[mt][0] = f2tf(odd ? y0 : x0);
                    af[mt][1] = f2tf(odd ? y1 : x1);
                    af[mt][2] = f2tf(odd ? y2 : x2);
                    af[mt][3] = f2tf(odd ? y3 : x3);
                }
#pragma unroll
                for (int nt2 = 0; nt2 < 8; nt2++) {
                    uint32_t bb2[2] = {
                        __float_as_uint(vc[(nt * 8 + t) * VSTRD + nt2 * 8 + g]),
                        __float_as_uint(vc[(nt * 8 + t + 4) * VSTRD + nt2 * 8 + g])};
                    mma8(vacc[0][nt2], af[0], bb2);
                    mma8(vacc[1][nt2], af[1], bb2);
                }
            }
            if (sc < 31) {
                float* kd = Kb + ((sc + 1) & 1) * A_KB_FL;
                float* vd = Vb + ((sc + 1) & 1) * A_VB_FL;
#pragma unroll
                for (int i = 0; i < 4; i++) {
                    st_tf(&kd[(lkey + i * 16) * KSTRD + ld4], kr[i]);
                    st_tf(&vd[(lkey + i * 16) * VSTRD + ld4], vr[i]);
                }
            }
        }
    }

    // write ctx
#pragma unroll
    for (int mt = 0; mt < 2; mt++) {
        size_t tok0 = (size_t)b * Nq + (q0 + w * 32 + mt * 16 + g);
        size_t tok1 = tok0 + 8;
#pragma unroll
        for (int nt2 = 0; nt2 < 8; nt2++) {
            int dc = h * Dq + nt2 * 8 + 2 * t;
            *(float2*)&g_ctx[tok0 * Cq + dc] =
                make_float2(vacc[mt][nt2][0], vacc[mt][nt2][1]);
            *(float2*)&g_ctx[tok1 * Cq + dc] =
                make_float2(vacc[mt][nt2][2], vacc[mt][nt2][3]);
        }
    }
}

// ===========================================================================
extern "C" void kernel_launch(void* const* d_in, const int* in_sizes, int n_in,
                              void* d_out, int out_size)
{
    const float* x      = (const float*)d_in[0];
    const float* w_qkv  = (const float*)d_in[1];
    const float* w_proj = (const float*)d_in[2];
    const float* b_proj = (const float*)d_in[3];

    const size_t out_elems  = (size_t)Mq * Cq;
    const size_t attn_elems = (size_t)BHq * Nq * (size_t)Nq;

    float* outp  = nullptr;
    float* attnp = nullptr;
    if ((size_t)out_size >= out_elems + attn_elems) {
        outp  = (float*)d_out;
        attnp = (float*)d_out + out_elems;
    } else if ((size_t)out_size == attn_elems) {
        attnp = (float*)d_out;
    } else {
        outp = (float*)d_out;
    }

    static const int gsm_bytes = G_SMEM_FLOATS * 4;
    cudaFuncSetAttribute(qkv_gemm_kernel, cudaFuncAttributeMaxDynamicSharedMemorySize,
                         gsm_bytes);
    cudaFuncSetAttribute(proj_gemm_kernel, cudaFuncAttributeMaxDynamicSharedMemorySize,
                         gsm_bytes);

    qkv_gemm_kernel<<<dim3(QKVq / 128, Mq / 128), 256, gsm_bytes>>>(x, w_qkv);

    static const int asm_bytes = A_SMEM_FLOATS * 4;   // 71680
    cudaFuncSetAttribute(attn_kernel, cudaFuncAttributeMaxDynamicSharedMemorySize,
                         asm_bytes);
    attn_kernel<<<dim3(Nq / 256, BHq), 256, asm_bytes>>>(attnp);

    if (outp) {
        proj_gemm_kernel<<<dim3(Cq / 128, Mq / 128), 256, gsm_bytes>>>(w_proj, b_proj, outp);
    }
}

// round 15
// speedup vs baseline: 1.0005x; 1.0003x over previous
#include <cuda_runtime.h>
#include <math.h>
#include <stdint.h>

#define Bq 8
#define Nq 2048
#define Cq 384
#define Hq 6
#define Dq 64
#define Mq (Bq * Nq)
#define QKVq (3 * Cq)
#define BHq (Bq * Hq)
#define LOG2E 1.4426950408889634f

__device__ float g_q[BHq * Nq * Dq];
__device__ float g_k[BHq * Nq * Dq];
__device__ float g_v[BHq * Nq * Dq];
__device__ float g_ctx[(size_t)Mq * Cq];

__device__ __forceinline__ uint32_t f2tf(float x) {
    uint32_t r;
    asm("cvt.rna.tf32.f32 %0, %1;" : "=r"(r) : "f"(x));
    return r;
}
__device__ __forceinline__ float tfv(float x) { return __uint_as_float(f2tf(x)); }
__device__ __forceinline__ float ex2(float x) {
    float r;
    asm("ex2.approx.f32 %0, %1;" : "=f"(r) : "f"(x));
    return r;
}
__device__ __forceinline__ void mma8(float* d, const uint32_t* a, const uint32_t* b) {
    asm volatile(
        "mma.sync.aligned.m16n8k8.row.col.f32.tf32.tf32.f32 "
        "{%0,%1,%2,%3},{%4,%5,%6,%7},{%8,%9},{%0,%1,%2,%3};"
        : "+f"(d[0]), "+f"(d[1]), "+f"(d[2]), "+f"(d[3])
        : "r"(a[0]), "r"(a[1]), "r"(a[2]), "r"(a[3]), "r"(b[0]), "r"(b[1]));
}
__device__ __forceinline__ void st_tf(float* d, float4 v) {
    d[0] = tfv(v.x); d[1] = tfv(v.y); d[2] = tfv(v.z); d[3] = tfv(v.w);
}

// ===========================================================================
// Shared GEMM core: single-tf32 both operands (unchanged from R8).
// ===========================================================================
#define GSTR 20
#define G_CH_FL (128 * GSTR)
#define G_SMEM_FLOATS (4 * G_CH_FL)

template <int KCHUNKS>
__device__ __forceinline__ void gemm_core(
    const float* __restrict__ x, const float* __restrict__ w,
    int m0, int j0, int K, float* smg, float acc[2][8][4])
{
    float* Xs = smg;
    float* Ws = smg + 2 * G_CH_FL;

    const int tid = threadIdx.x, lane = tid & 31, wp = tid >> 5;
    const int g = lane >> 2, t = lane & 3;
    const int wm = wp & 3, wn = wp >> 2;

#pragma unroll
    for (int a = 0; a < 2; a++)
#pragma unroll
        for (int b = 0; b < 8; b++)
#pragma unroll
            for (int c = 0; c < 4; c++) acc[a][b][c] = 0.f;

    float4 xr[2], wr[2];
#pragma unroll
    for (int i = 0; i < 2; i++) {
        int f = tid + i * 256;
        int row = f >> 2, c4 = (f & 3) * 4;
        xr[i] = *(const float4*)&x[(size_t)(m0 + row) * K + c4];
        wr[i] = *(const float4*)&w[(size_t)(j0 + row) * K + c4];
    }
#pragma unroll
    for (int i = 0; i < 2; i++) {
        int f = tid + i * 256;
        int row = f >> 2, c4 = (f & 3) * 4;
        st_tf(&Xs[row * GSTR + c4], xr[i]);
        st_tf(&Ws[row * GSTR + c4], wr[i]);
    }

    for (int ch = 0; ch < KCHUNKS; ch++) {
        if (ch < KCHUNKS - 1) {
            int k0 = (ch + 1) * 16;
#pragma unroll
            for (int i = 0; i < 2; i++) {
                int f = tid + i * 256;
                int row = f >> 2, c4 = (f & 3) * 4;
                xr[i] = *(const float4*)&x[(size_t)(m0 + row) * K + k0 + c4];
                wr[i] = *(const float4*)&w[(size_t)(j0 + row) * K + k0 + c4];
            }
        }
        __syncthreads();
        const float* Xc = Xs + (ch & 1) * G_CH_FL;
        const float* Wc = Ws + (ch & 1) * G_CH_FL;

#pragma unroll
        for (int ks = 0; ks < 2; ks++) {
            uint32_t af[2][4];
#pragma unroll
            for (int mt = 0; mt < 2; mt++) {
                int r = wm * 32 + mt * 16;
                af[mt][0] = __float_as_uint(Xc[(r + g) * GSTR + ks * 8 + t]);
                af[mt][1] = __float_as_uint(Xc[(r + g + 8) * GSTR + ks * 8 + t]);
                af[mt][2] = __float_as_uint(Xc[(r + g) * GSTR + ks * 8 + t + 4]);
                af[mt][3] = __float_as_uint(Xc[(r + g + 8) * GSTR + ks * 8 + t + 4]);
            }
#pragma unroll
            for (int nt = 0; nt < 8; nt++) {
                int c = wn * 64 + nt * 8;
                uint32_t bw[2] = {
                    __float_as_uint(Wc[(c + g) * GSTR + ks * 8 + t]),
                    __float_as_uint(Wc[(c + g) * GSTR + ks * 8 + t + 4])};
                mma8(acc[0][nt], af[0], bw);
                mma8(acc[1][nt], af[1], bw);
            }
        }
        if (ch < KCHUNKS - 1) {
            float* Xd = Xs + ((ch + 1) & 1) * G_CH_FL;
            float* Wd = Ws + ((ch + 1) & 1) * G_CH_FL;
#pragma unroll
            for (int i = 0; i < 2; i++) {
                int f = tid + i * 256;
                int row = f >> 2, c4 = (f & 3) * 4;
                st_tf(&Xd[row * GSTR + c4], xr[i]);
                st_tf(&Wd[row * GSTR + c4], wr[i]);
            }
        }
    }
}

__global__ __launch_bounds__(256, 2) void qkv_gemm_kernel(
    const float* __restrict__ x, const float* __restrict__ wq)
{
    extern __shared__ float smg[];
    float acc[2][8][4];
    const int m0 = blockIdx.y * 128, j0 = blockIdx.x * 128;
    gemm_core<24>(x, wq, m0, j0, Cq, smg, acc);

    const int tid = threadIdx.x, lane = tid & 31, wp = tid >> 5;
    const int g = lane >> 2, t = lane & 3;
    const int wm = wp & 3, wn = wp >> 2;

#pragma unroll
    for (int nt = 0; nt < 8; nt++) {
        int j = j0 + wn * 64 + nt * 8 + 2 * t;
        int s = j / Cq;
        int jj = j - s * Cq;
        int h = jj >> 6, d = jj & 63;
        float* dst = (s == 0) ? g_q : ((s == 1) ? g_k : g_v);
#pragma unroll
        for (int mt = 0; mt < 2; mt++) {
            int m = m0 + wm * 32 + mt * 16 + g;
            int bb = m >> 11, nn = m & (Nq - 1);
            *(float2*)&dst[(((size_t)bb * Hq + h) * Nq + nn) * Dq + d] =
                make_float2(acc[mt][nt][0], acc[mt][nt][1]);
            m += 8; bb = m >> 11; nn = m & (Nq - 1);
            *(float2*)&dst[(((size_t)bb * Hq + h) * Nq + nn) * Dq + d] =
                make_float2(acc[mt][nt][2], acc[mt][nt][3]);
        }
    }
}

__global__ __launch_bounds__(256, 2) void proj_gemm_kernel(
    const float* __restrict__ w, const float* __restrict__ bias,
    float* __restrict__ out)
{
    extern __shared__ float smg[];
    float acc[2][8][4];
    const int m0 = blockIdx.y * 128, j0 = blockIdx.x * 128;
    gemm_core<24>(g_ctx, w, m0, j0, Cq, smg, acc);

    const int tid = threadIdx.x, lane = tid & 31, wp = tid >> 5;
    const int g = lane >> 2, t = lane & 3;
    const int wm = wp & 3, wn = wp >> 2;

#pragma unroll
    for (int nt = 0; nt < 8; nt++) {
        int j = j0 + wn * 64 + nt * 8 + 2 * t;
        float2 bv = *(const float2*)&bias[j];
#pragma unroll
        for (int mt = 0; mt < 2; mt++) {
            int m = m0 + wm * 32 + mt * 16 + g;
            *(float2*)&out[(size_t)m * Cq + j] =
                make_float2(acc[mt][nt][0] + bv.x, acc[mt][nt][1] + bv.y);
            *(float2*)&out[(size_t)(m + 8) * Cq + j] =
                make_float2(acc[mt][nt][2] + bv.x, acc[mt][nt][3] + bv.y);
        }
    }
}

// ===========================================================================
// Kernel 2: fused attention v4.
// CTA = (b,h) x 256 rows; 256 threads (8 warps x 32 rows = 2 m16 tiles each).
// B-fragments (K and V) loaded once per warp feed BOTH m-tiles -> LDS halved.
// Q A-fragments from gmem; K/V double-buffered in smem (R5 strides, no permute).
// ===========================================================================
#define KSTRD 68
#define VSTRD 72
#define A_KB_FL (64 * KSTRD)
#define A_VB_FL (64 * VSTRD)
#define A_SMEM_FLOATS (2 * A_KB_FL + 2 * A_VB_FL)   // 17920 fl = 71680 B

__global__ __launch_bounds__(256, 1) void attn_kernel(float* __restrict__ attnp)
{
    extern __shared__ float sma[];
    float* Kb = sma;                  // [2][64][KSTRD]
    float* Vb = sma + 2 * A_KB_FL;    // [2][64][VSTRD]

    const int tid = threadIdx.x, lane = tid & 31, w = tid >> 5;
    const int g = lane >> 2, t = lane & 3;
    const int bh = blockIdx.y, q0 = blockIdx.x * 256;
    const int b = bh / Hq, h = bh - b * Hq;

    const float* qptr = g_q + (size_t)bh * Nq * Dq;
    const float* kptr = g_k + (size_t)bh * Nq * Dq;
    const float* vptr = g_v + (size_t)bh * Nq * Dq;

    // ---- Q A-fragments from gmem: warp w owns rows w*32 .. w*32+31 ----
    const float qsc = 0.125f * LOG2E;
    uint32_t Ah[2][8][4];
#pragma unroll
    for (int mt = 0; mt < 2; mt++) {
        const float* q0p = qptr + (size_t)(q0 + w * 32 + mt * 16 + g) * Dq;
        const float* q1p = q0p + 8 * Dq;
#pragma unroll
        for (int ks = 0; ks < 8; ks++) {
            int dd = ks * 8 + t;
            Ah[mt][ks][0] = f2tf(q0p[dd] * qsc);
            Ah[mt][ks][1] = f2tf(q1p[dd] * qsc);
            Ah[mt][ks][2] = f2tf(q0p[dd + 4] * qsc);
            Ah[mt][ks][3] = f2tf(q1p[dd + 4] * qsc);
        }
    }

    // loader mapping: 1024 float4 per matrix per chunk, 4 per thread
    const int lkey = tid >> 4, ld4 = (tid & 15) * 4;   // keys 0..15 (+16 stride), d 0..60

    // ================= pass 1: row sums =================
    float l0[2] = {0.f, 0.f}, l1[2] = {0.f, 0.f};
    {
        float4 kr[4];
#pragma unroll
        for (int i = 0; i < 4; i++) {
            int key = lkey + i * 16;
            kr[i] = *(const float4*)&kptr[(size_t)key * Dq + ld4];
        }
#pragma unroll
        for (int i = 0; i < 4; i++)
            st_tf(&Kb[(lkey + i * 16) * KSTRD + ld4], kr[i]);

        for (int sc = 0; sc < 32; sc++) {
            if (sc < 31) {
                const float* kp = kptr + (size_t)(sc + 1) * 64 * Dq;
#pragma unroll
                for (int i = 0; i < 4; i++)
                    kr[i] = *(const float4*)&kp[(size_t)(lkey + i * 16) * Dq + ld4];
            }
            __syncthreads();
            const float* kc = Kb + (sc & 1) * A_KB_FL;
#pragma unroll
            for (int nt = 0; nt < 8; nt++) {
                float a4[2][4] = {{0.f, 0.f, 0.f, 0.f}, {0.f, 0.f, 0.f, 0.f}};
#pragma unroll
                for (int ks = 0; ks < 8; ks++) {
                    uint32_t bb[2] = {
                        __float_as_uint(kc[(nt * 8 + g) * KSTRD + ks * 8 + t]),
                        __float_as_uint(kc[(nt * 8 + g) * KSTRD + ks * 8 + t + 4])};
                    mma8(a4[0], Ah[0][ks], bb);
                    mma8(a4[1], Ah[1][ks], bb);
                }
#pragma unroll
                for (int mt = 0; mt < 2; mt++) {
                    l0[mt] += ex2(a4[mt][0]) + ex2(a4[mt][1]);
                    l1[mt] += ex2(a4[mt][2]) + ex2(a4[mt][3]);
                }
            }
            if (sc < 31) {
                float* kd = Kb + ((sc + 1) & 1) * A_KB_FL;
#pragma unroll
                for (int i = 0; i < 4; i++)
                    st_tf(&kd[(lkey + i * 16) * KSTRD + ld4], kr[i]);
            }
        }
    }
    float rinv0[2], rinv1[2];
#pragma unroll
    for (int mt = 0; mt < 2; mt++) {
        float a = l0[mt], c = l1[mt];
        a += __shfl_xor_sync(0xffffffffu, a, 1);
        a += __shfl_xor_sync(0xffffffffu, a, 2);
        c += __shfl_xor_sync(0xffffffffu, c, 1);
        c += __shfl_xor_sync(0xffffffffu, c, 2);
        rinv0[mt] = 1.f / a;
        rinv1[mt] = 1.f / c;
    }

    // ================= pass 2: attn + PV =================
    float vacc[2][8][4];
#pragma unroll
    for (int mt = 0; mt < 2; mt++)
#pragma unroll
        for (int d = 0; d < 8; d++)
#pragma unroll
            for (int j = 0; j < 4; j++) vacc[mt][d][j] = 0.f;

    float* ap[2] = {
        attnp ? attnp + ((size_t)bh * Nq + (q0 + w * 32 + g)) * (size_t)Nq : (float*)0,
        attnp ? attnp + ((size_t)bh * Nq + (q0 + w * 32 + 16 + g)) * (size_t)Nq : (float*)0};

    {
        float4 kr[4], vr[4];
#pragma unroll
        for (int i = 0; i < 4; i++) {
            int key = lkey + i * 16;
            kr[i] = *(const float4*)&kptr[(size_t)key * Dq + ld4];
            vr[i] = *(const float4*)&vptr[(size_t)key * Dq + ld4];
        }
        __syncthreads();   // pass-1 reads complete before overwrite
#pragma unroll
        for (int i = 0; i < 4; i++) {
            st_tf(&Kb[(lkey + i * 16) * KSTRD + ld4], kr[i]);
            st_tf(&Vb[(lkey + i * 16) * VSTRD + ld4], vr[i]);
        }

        const int L0 = g * 4 + (t >> 1);
        const int L1 = L0 + 2;
        const bool odd = (t & 1);

        for (int sc = 0; sc < 32; sc++) {
            if (sc < 31) {
                const float* kp = kptr + (size_t)(sc + 1) * 64 * Dq;
                const float* vp = vptr + (size_t)(sc + 1) * 64 * Dq;
#pragma unroll
                for (int i = 0; i < 4; i++) {
                    kr[i] = *(const float4*)&kp[(size_t)(lkey + i * 16) * Dq + ld4];
                    vr[i] = *(const float4*)&vp[(size_t)(lkey + i * 16) * Dq + ld4];
                }
            }
            __syncthreads();
            const float* kc = Kb + (sc & 1) * A_KB_FL;
            const float* vc = Vb + (sc & 1) * A_VB_FL;

#pragma unroll
            for (int nt = 0; nt < 8; nt++) {
                float a4[2][4] = {{0.f, 0.f, 0.f, 0.f}, {0.f, 0.f, 0.f, 0.f}};
#pragma unroll
                for (int ks = 0; ks < 8; ks++) {
                    uint32_t bb[2] = {
                        __float_as_uint(kc[(nt * 8 + g) * KSTRD + ks * 8 + t]),
                        __float_as_uint(kc[(nt * 8 + g) * KSTRD + ks * 8 + t + 4])};
                    mma8(a4[0], Ah[0][ks], bb);
                    mma8(a4[1], Ah[1][ks], bb);
                }
                int col = sc * 64 + nt * 8 + 2 * t;
                uint32_t af[2][4];
#pragma unroll
                for (int mt = 0; mt < 2; mt++) {
                    float p0 = ex2(a4[mt][0]) * rinv0[mt];
                    float p1 = ex2(a4[mt][1]) * rinv0[mt];
                    float p2 = ex2(a4[mt][2]) * rinv1[mt];
                    float p3 = ex2(a4[mt][3]) * rinv1[mt];
                    if (ap[mt]) {
                        *(float2*)&ap[mt][col] = make_float2(p0, p1);
                        *(float2*)&ap[mt][8 * (size_t)Nq + col] = make_float2(p2, p3);
                    }
                    float x0 = __shfl_sync(0xffffffffu, p0, L0);
                    float y0 = __shfl_sync(0xffffffffu, p1, L0);
                    float x1 = __shfl_sync(0xffffffffu, p2, L0);
                    float y1 = __shfl_sync(0xffffffffu, p3, L0);
                    float x2 = __shfl_sync(0xffffffffu, p0, L1);
                    float y2 = __shfl_sync(0xffffffffu, p1, L1);
                    float x3 = __shfl_sync(0xffffffffu, p2, L1);
                    float y3 = __shfl_sync(0xffffffffu, p3, L1);
                    af[mt][0] = f2tf(odd ? y0 : x0);
                    af[mt][1] = f2tf(odd ? y1 : x1);
                    af[mt][2] = f2tf(odd ? y2 : x2);
                    af[mt][3] = f2tf(odd ? y3 : x3);
                }
#pragma unroll
                for (int nt2 = 0; nt2 < 8; nt2++) {
                    uint32_t bb2[2] = {
                        __float_as_uint(vc[(nt * 8 + t) * VSTRD + nt2 * 8 + g]),
                        __float_as_uint(vc[(nt * 8 + t + 4) * VSTRD + nt2 * 8 + g])};
                    mma8(vacc[0][nt2], af[0], bb2);
                    mma8(vacc[1][nt2], af[1], bb2);
                }
            }
            if (sc < 31) {
                float* kd = Kb + ((sc + 1) & 1) * A_KB_FL;
                float* vd = Vb + ((sc + 1) & 1) * A_VB_FL;
#pragma unroll
                for (int i = 0; i < 4; i++) {
                    st_tf(&kd[(lkey + i * 16) * KSTRD + ld4], kr[i]);
                    st_tf(&vd[(lkey + i * 16) * VSTRD + ld4], vr[i]);
                }
            }
        }
    }

    // write ctx
#pragma unroll
    for (int mt = 0; mt < 2; mt++) {
        size_t tok0 = (size_t)b * Nq + (q0 + w * 32 + mt * 16 + g);
        size_t tok1 = tok0 + 8;
#pragma unroll
        for (int nt2 = 0; nt2 < 8; nt2++) {
            int dc = h * Dq + nt2 * 8 + 2 * t;
            *(float2*)&g_ctx[tok0 * Cq + dc] =
                make_float2(vacc[mt][nt2][0], vacc[mt][nt2][1]);
            *(float2*)&g_ctx[tok1 * Cq + dc] =
                make_float2(vacc[mt][nt2][2], vacc[mt][nt2][3]);
        }
    }
}

// ===========================================================================
extern "C" void kernel_launch(void* const* d_in, const int* in_sizes, int n_in,
                              void* d_out, int out_size)
{
    const float* x      = (const float*)d_in[0];
    const float* w_qkv  = (const float*)d_in[1];
    const float* w_proj = (const float*)d_in[2];
    const float* b_proj = (const float*)d_in[3];

    const size_t out_elems  = (size_t)Mq * Cq;
    const size_t attn_elems = (size_t)BHq * Nq * (size_t)Nq;

    float* outp  = nullptr;
    float* attnp = nullptr;
    if ((size_t)out_size >= out_elems + attn_elems) {
        outp  = (float*)d_out;
        attnp = (float*)d_out + out_elems;
    } else if ((size_t)out_size == attn_elems) {
        attnp = (float*)d_out;
    } else {
        outp = (float*)d_out;
    }

    static const int gsm_bytes = G_SMEM_FLOATS * 4;
    cudaFuncSetAttribute(qkv_gemm_kernel, cudaFuncAttributeMaxDynamicSharedMemorySize,
                         gsm_bytes);
    cudaFuncSetAttribute(proj_gemm_kernel, cudaFuncAttributeMaxDynamicSharedMemorySize,
                         gsm_bytes);

    qkv_gemm_kernel<<<dim3(QKVq / 128, Mq / 128), 256, gsm_bytes>>>(x, w_qkv);

    static const int asm_bytes = A_SMEM_FLOATS * 4;   // 71680
    cudaFuncSetAttribute(attn_kernel, cudaFuncAttributeMaxDynamicSharedMemorySize,
                         asm_bytes);
    attn_kernel<<<dim3(Nq / 256, BHq), 256, asm_bytes>>>(attnp);

    if (outp) {
        proj_gemm_kernel<<<dim3(Cq / 128, Mq / 128), 256, gsm_bytes>>>(w_proj, b_proj, outp);
    }
}

// round 16
// speedup vs baseline: 1.0014x; 1.0010x over previous
#include <cuda_runtime.h>
#include <math.h>
#include <stdint.h>

#define Bq 8
#define Nq 2048
#define Cq 384
#define Hq 6
#define Dq 64
#define Mq (Bq * Nq)
#define QKVq (3 * Cq)
#define BHq (Bq * Hq)
#define LOG2E 1.4426950408889634f

__device__ float g_q[BHq * Nq * Dq];
__device__ float g_k[BHq * Nq * Dq];
__device__ float g_v[BHq * Nq * Dq];
__device__ float g_ctx[(size_t)Mq * Cq];

__device__ __forceinline__ uint32_t f2tf(float x) {
    uint32_t r;
    asm("cvt.rna.tf32.f32 %0, %1;" : "=r"(r) : "f"(x));
    return r;
}
__device__ __forceinline__ float tfv(float x) { return __uint_as_float(f2tf(x)); }
__device__ __forceinline__ float ex2(float x) {
    float r;
    asm("ex2.approx.f32 %0, %1;" : "=f"(r) : "f"(x));
    return r;
}
__device__ __forceinline__ void mma8(float* d, const uint32_t* a, const uint32_t* b) {
    asm volatile(
        "mma.sync.aligned.m16n8k8.row.col.f32.tf32.tf32.f32 "
        "{%0,%1,%2,%3},{%4,%5,%6,%7},{%8,%9},{%0,%1,%2,%3};"
        : "+f"(d[0]), "+f"(d[1]), "+f"(d[2]), "+f"(d[3])
        : "r"(a[0]), "r"(a[1]), "r"(a[2]), "r"(a[3]), "r"(b[0]), "r"(b[1]));
}
__device__ __forceinline__ void st_tf(float* d, float4 v) {
    d[0] = tfv(v.x); d[1] = tfv(v.y); d[2] = tfv(v.z); d[3] = tfv(v.w);
}

// ===========================================================================
// Shared GEMM core: single-tf32 both operands (unchanged from R8).
// ===========================================================================
#define GSTR 20
#define G_CH_FL (128 * GSTR)
#define G_SMEM_FLOATS (4 * G_CH_FL)

template <int KCHUNKS>
__device__ __forceinline__ void gemm_core(
    const float* __restrict__ x, const float* __restrict__ w,
    int m0, int j0, int K, float* smg, float acc[2][8][4])
{
    float* Xs = smg;
    float* Ws = smg + 2 * G_CH_FL;

    const int tid = threadIdx.x, lane = tid & 31, wp = tid >> 5;
    const int g = lane >> 2, t = lane & 3;
    const int wm = wp & 3, wn = wp >> 2;

#pragma unroll
    for (int a = 0; a < 2; a++)
#pragma unroll
        for (int b = 0; b < 8; b++)
#pragma unroll
            for (int c = 0; c < 4; c++) acc[a][b][c] = 0.f;

    float4 xr[2], wr[2];
#pragma unroll
    for (int i = 0; i < 2; i++) {
        int f = tid + i * 256;
        int row = f >> 2, c4 = (f & 3) * 4;
        xr[i] = *(const float4*)&x[(size_t)(m0 + row) * K + c4];
        wr[i] = *(const float4*)&w[(size_t)(j0 + row) * K + c4];
    }
#pragma unroll
    for (int i = 0; i < 2; i++) {
        int f = tid + i * 256;
        int row = f >> 2, c4 = (f & 3) * 4;
        st_tf(&Xs[row * GSTR + c4], xr[i]);
        st_tf(&Ws[row * GSTR + c4], wr[i]);
    }

    for (int ch = 0; ch < KCHUNKS; ch++) {
        if (ch < KCHUNKS - 1) {
            int k0 = (ch + 1) * 16;
#pragma unroll
            for (int i = 0; i < 2; i++) {
                int f = tid + i * 256;
                int row = f >> 2, c4 = (f & 3) * 4;
                xr[i] = *(const float4*)&x[(size_t)(m0 + row) * K + k0 + c4];
                wr[i] = *(const float4*)&w[(size_t)(j0 + row) * K + k0 + c4];
            }
        }
        __syncthreads();
        const float* Xc = Xs + (ch & 1) * G_CH_FL;
        const float* Wc = Ws + (ch & 1) * G_CH_FL;

#pragma unroll
        for (int ks = 0; ks < 2; ks++) {
            uint32_t af[2][4];
#pragma unroll
            for (int mt = 0; mt < 2; mt++) {
                int r = wm * 32 + mt * 16;
                af[mt][0] = __float_as_uint(Xc[(r + g) * GSTR + ks * 8 + t]);
                af[mt][1] = __float_as_uint(Xc[(r + g + 8) * GSTR + ks * 8 + t]);
                af[mt][2] = __float_as_uint(Xc[(r + g) * GSTR + ks * 8 + t + 4]);
                af[mt][3] = __float_as_uint(Xc[(r + g + 8) * GSTR + ks * 8 + t + 4]);
            }
#pragma unroll
            for (int nt = 0; nt < 8; nt++) {
                int c = wn * 64 + nt * 8;
                uint32_t bw[2] = {
                    __float_as_uint(Wc[(c + g) * GSTR + ks * 8 + t]),
                    __float_as_uint(Wc[(c + g) * GSTR + ks * 8 + t + 4])};
                mma8(acc[0][nt], af[0], bw);
                mma8(acc[1][nt], af[1], bw);
            }
        }
        if (ch < KCHUNKS - 1) {
            float* Xd = Xs + ((ch + 1) & 1) * G_CH_FL;
            float* Wd = Ws + ((ch + 1) & 1) * G_CH_FL;
#pragma unroll
            for (int i = 0; i < 2; i++) {
                int f = tid + i * 256;
                int row = f >> 2, c4 = (f & 3) * 4;
                st_tf(&Xd[row * GSTR + c4], xr[i]);
                st_tf(&Wd[row * GSTR + c4], wr[i]);
            }
        }
    }
}

__global__ __launch_bounds__(256, 2) void qkv_gemm_kernel(
    const float* __restrict__ x, const float* __restrict__ wq)
{
    extern __shared__ float smg[];
    float acc[2][8][4];
    const int m0 = blockIdx.y * 128, j0 = blockIdx.x * 128;
    gemm_core<24>(x, wq, m0, j0, Cq, smg, acc);

    const int tid = threadIdx.x, lane = tid & 31, wp = tid >> 5;
    const int g = lane >> 2, t = lane & 3;
    const int wm = wp & 3, wn = wp >> 2;

#pragma unroll
    for (int nt = 0; nt < 8; nt++) {
        int j = j0 + wn * 64 + nt * 8 + 2 * t;
        int s = j / Cq;
        int jj = j - s * Cq;
        int h = jj >> 6, d = jj & 63;
        float* dst = (s == 0) ? g_q : ((s == 1) ? g_k : g_v);
#pragma unroll
        for (int mt = 0; mt < 2; mt++) {
            int m = m0 + wm * 32 + mt * 16 + g;
            int bb = m >> 11, nn = m & (Nq - 1);
            *(float2*)&dst[(((size_t)bb * Hq + h) * Nq + nn) * Dq + d] =
                make_float2(acc[mt][nt][0], acc[mt][nt][1]);
            m += 8; bb = m >> 11; nn = m & (Nq - 1);
            *(float2*)&dst[(((size_t)bb * Hq + h) * Nq + nn) * Dq + d] =
                make_float2(acc[mt][nt][2], acc[mt][nt][3]);
        }
    }
}

__global__ __launch_bounds__(256, 2) void proj_gemm_kernel(
    const float* __restrict__ w, const float* __restrict__ bias,
    float* __restrict__ out)
{
    extern __shared__ float smg[];
    float acc[2][8][4];
    const int m0 = blockIdx.y * 128, j0 = blockIdx.x * 128;
    gemm_core<24>(g_ctx, w, m0, j0, Cq, smg, acc);

    const int tid = threadIdx.x, lane = tid & 31, wp = tid >> 5;
    const int g = lane >> 2, t = lane & 3;
    const int wm = wp & 3, wn = wp >> 2;

#pragma unroll
    for (int nt = 0; nt < 8; nt++) {
        int j = j0 + wn * 64 + nt * 8 + 2 * t;
        float2 bv = *(const float2*)&bias[j];
#pragma unroll
        for (int mt = 0; mt < 2; mt++) {
            int m = m0 + wm * 32 + mt * 16 + g;
            *(float2*)&out[(size_t)m * Cq + j] =
                make_float2(acc[mt][nt][0] + bv.x, acc[mt][nt][1] + bv.y);
            *(float2*)&out[(size_t)(m + 8) * Cq + j] =
                make_float2(acc[mt][nt][2] + bv.x, acc[mt][nt][3] + bv.y);
        }
    }
}

// ===========================================================================
// Kernel 2: fused attention v4.
// CTA = (b,h) x 256 rows; 256 threads (8 warps x 32 rows = 2 m16 tiles each).
// B-fragments (K and V) loaded once per warp feed BOTH m-tiles -> LDS halved.
// Q A-fragments from gmem; K/V double-buffered in smem (R5 strides, no permute).
// ===========================================================================
#define KSTRD 68
#define VSTRD 72
#define A_KB_FL (64 * KSTRD)
#define A_VB_FL (64 * VSTRD)
#define A_SMEM_FLOATS (2 * A_KB_FL + 2 * A_VB_FL)   // 17920 fl = 71680 B

__global__ __launch_bounds__(256, 1) void attn_kernel(float* __restrict__ attnp)
{
    extern __shared__ float sma[];
    float* Kb = sma;                  // [2][64][KSTRD]
    float* Vb = sma + 2 * A_KB_FL;    // [2][64][VSTRD]

    const int tid = threadIdx.x, lane = tid & 31, w = tid >> 5;
    const int g = lane >> 2, t = lane & 3;
    const int bh = blockIdx.y, q0 = blockIdx.x * 256;
    const int b = bh / Hq, h = bh - b * Hq;

    const float* qptr = g_q + (size_t)bh * Nq * Dq;
    const float* kptr = g_k + (size_t)bh * Nq * Dq;
    const float* vptr = g_v + (size_t)bh * Nq * Dq;

    // ---- Q A-fragments from gmem: warp w owns rows w*32 .. w*32+31 ----
    const float qsc = 0.125f * LOG2E;
    uint32_t Ah[2][8][4];
#pragma unroll
    for (int mt = 0; mt < 2; mt++) {
        const float* q0p = qptr + (size_t)(q0 + w * 32 + mt * 16 + g) * Dq;
        const float* q1p = q0p + 8 * Dq;
#pragma unroll
        for (int ks = 0; ks < 8; ks++) {
            int dd = ks * 8 + t;
            Ah[mt][ks][0] = f2tf(q0p[dd] * qsc);
            Ah[mt][ks][1] = f2tf(q1p[dd] * qsc);
            Ah[mt][ks][2] = f2tf(q0p[dd + 4] * qsc);
            Ah[mt][ks][3] = f2tf(q1p[dd + 4] * qsc);
        }
    }

    // loader mapping: 1024 float4 per matrix per chunk, 4 per thread
    const int lkey = tid >> 4, ld4 = (tid & 15) * 4;   // keys 0..15 (+16 stride), d 0..60

    // ================= pass 1: row sums =================
    float l0[2] = {0.f, 0.f}, l1[2] = {0.f, 0.f};
    {
        float4 kr[4];
#pragma unroll
        for (int i = 0; i < 4; i++) {
            int key = lkey + i * 16;
            kr[i] = *(const float4*)&kptr[(size_t)key * Dq + ld4];
        }
#pragma unroll
        for (int i = 0; i < 4; i++)
            st_tf(&Kb[(lkey + i * 16) * KSTRD + ld4], kr[i]);

        for (int sc = 0; sc < 32; sc++) {
            if (sc < 31) {
                const float* kp = kptr + (size_t)(sc + 1) * 64 * Dq;
#pragma unroll
                for (int i = 0; i < 4; i++)
                    kr[i] = *(const float4*)&kp[(size_t)(lkey + i * 16) * Dq + ld4];
            }
            __syncthreads();
            const float* kc = Kb + (sc & 1) * A_KB_FL;
#pragma unroll
            for (int nt = 0; nt < 8; nt++) {
                float a4[2][4] = {{0.f, 0.f, 0.f, 0.f}, {0.f, 0.f, 0.f, 0.f}};
#pragma unroll
                for (int ks = 0; ks < 8; ks++) {
                    uint32_t bb[2] = {
                        __float_as_uint(kc[(nt * 8 + g) * KSTRD + ks * 8 + t]),
                        __float_as_uint(kc[(nt * 8 + g) * KSTRD + ks * 8 + t + 4])};
                    mma8(a4[0], Ah[0][ks], bb);
                    mma8(a4[1], Ah[1][ks], bb);
                }
#pragma unroll
                for (int mt = 0; mt < 2; mt++) {
                    l0[mt] += ex2(a4[mt][0]) + ex2(a4[mt][1]);
                    l1[mt] += ex2(a4[mt][2]) + ex2(a4[mt][3]);
                }
            }
            if (sc < 31) {
                float* kd = Kb + ((sc + 1) & 1) * A_KB_FL;
#pragma unroll
                for (int i = 0; i < 4; i++)
                    st_tf(&kd[(lkey + i * 16) * KSTRD + ld4], kr[i]);
            }
        }
    }
    float rinv0[2], rinv1[2];
#pragma unroll
    for (int mt = 0; mt < 2; mt++) {
        float a = l0[mt], c = l1[mt];
        a += __shfl_xor_sync(0xffffffffu, a, 1);
        a += __shfl_xor_sync(0xffffffffu, a, 2);
        c += __shfl_xor_sync(0xffffffffu, c, 1);
        c += __shfl_xor_sync(0xffffffffu, c, 2);
        rinv0[mt] = 1.f / a;
        rinv1[mt] = 1.f / c;
    }

    // ================= pass 2: attn + PV =================
    float vacc[2][8][4];
#pragma unroll
    for (int mt = 0; mt < 2; mt++)
#pragma unroll
        for (int d = 0; d < 8; d++)
#pragma unroll
            for (int j = 0; j < 4; j++) vacc[mt][d][j] = 0.f;

    float* ap[2] = {
        attnp ? attnp + ((size_t)bh * Nq + (q0 + w * 32 + g)) * (size_t)Nq : (float*)0,
        attnp ? attnp + ((size_t)bh * Nq + (q0 + w * 32 + 16 + g)) * (size_t)Nq : (float*)0};

    {
        float4 kr[4], vr[4];
#pragma unroll
        for (int i = 0; i < 4; i++) {
            int key = lkey + i * 16;
            kr[i] = *(const float4*)&kptr[(size_t)key * Dq + ld4];
            vr[i] = *(const float4*)&vptr[(size_t)key * Dq + ld4];
        }
        __syncthreads();   // pass-1 reads complete before overwrite
#pragma unroll
        for (int i = 0; i < 4; i++) {
            st_tf(&Kb[(lkey + i * 16) * KSTRD + ld4], kr[i]);
            st_tf(&Vb[(lkey + i * 16) * VSTRD + ld4], vr[i]);
        }

        const int L0 = g * 4 + (t >> 1);
        const int L1 = L0 + 2;
        const bool odd = (t & 1);

        for (int sc = 0; sc < 32; sc++) {
            if (sc < 31) {
                const float* kp = kptr + (size_t)(sc + 1) * 64 * Dq;
                const float* vp = vptr + (size_t)(sc + 1) * 64 * Dq;
#pragma unroll
                for (int i = 0; i < 4; i++) {
                    kr[i] = *(const float4*)&kp[(size_t)(lkey + i * 16) * Dq + ld4];
                    vr[i] = *(const float4*)&vp[(size_t)(lkey + i * 16) * Dq + ld4];
                }
            }
            __syncthreads();
            const float* kc = Kb + (sc & 1) * A_KB_FL;
            const float* vc = Vb + (sc & 1) * A_VB_FL;

#pragma unroll
            for (int nt = 0; nt < 8; nt++) {
                float a4[2][4] = {{0.f, 0.f, 0.f, 0.f}, {0.f, 0.f, 0.f, 0.f}};
#pragma unroll
                for (int ks = 0; ks < 8; ks++) {
                    uint32_t bb[2] = {
                        __float_as_uint(kc[(nt * 8 + g) * KSTRD + ks * 8 + t]),
                        __float_as_uint(kc[(nt * 8 + g) * KSTRD + ks * 8 + t + 4])};
                    mma8(a4[0], Ah[0][ks], bb);
                    mma8(a4[1], Ah[1][ks], bb);
                }
                int col = sc * 64 + nt * 8 + 2 * t;
                uint32_t af[2][4];
#pragma unroll
                for (int mt = 0; mt < 2; mt++) {
                    float p0 = ex2(a4[mt][0]) * rinv0[mt];
                    float p1 = ex2(a4[mt][1]) * rinv0[mt];
                    float p2 = ex2(a4[mt][2]) * rinv1[mt];
                    float p3 = ex2(a4[mt][3]) * rinv1[mt];
                    if (ap[mt]) {
                        *(float2*)&ap[mt][col] = make_float2(p0, p1);
                        *(float2*)&ap[mt][8 * (size_t)Nq + col] = make_float2(p2, p3);
                    }
                    float x0 = __shfl_sync(0xffffffffu, p0, L0);
                    float y0 = __shfl_sync(0xffffffffu, p1, L0);
                    float x1 = __shfl_sync(0xffffffffu, p2, L0);
                    float y1 = __shfl_sync(0xffffffffu, p3, L0);
                    float x2 = __shfl_sync(0xffffffffu, p0, L1);
                    float y2 = __shfl_sync(0xffffffffu, p1, L1);
                    float x3 = __shfl_sync(0xffffffffu, p2, L1);
                    float y3 = __shfl_sync(0xffffffffu, p3, L1);
                    af[mt][0] = f2tf(odd ? y0 : x0);
                    af[mt][1] = f2tf(odd ? y1 : x1);
                    af[mt][2] = f2tf(odd ? y2 : x2);
                    af[mt][3] = f2tf(odd ? y3 : x3);
                }
#pragma unroll
                for (int nt2 = 0; nt2 < 8; nt2++) {
                    uint32_t bb2[2] = {
                        __float_as_uint(vc[(nt * 8 + t) * VSTRD + nt2 * 8 + g]),
                        __float_as_uint(vc[(nt * 8 + t + 4) * VSTRD + nt2 * 8 + g])};
                    mma8(vacc[0][nt2], af[0], bb2);
                    mma8(vacc[1][nt2], af[1], bb2);
                }
            }
            if (sc < 31) {
                float* kd = Kb + ((sc + 1) & 1) * A_KB_FL;
                float* vd = Vb + ((sc + 1) & 1) * A_VB_FL;
#pragma unroll
                for (int i = 0; i < 4; i++) {
                    st_tf(&kd[(lkey + i * 16) * KSTRD + ld4], kr[i]);
                    st_tf(&vd[(lkey + i * 16) * VSTRD + ld4], vr[i]);
                }
            }
        }
    }

    // write ctx
#pragma unroll
    for (int mt = 0; mt < 2; mt++) {
        size_t tok0 = (size_t)b * Nq + (q0 + w * 32 + mt * 16 + g);
        size_t tok1 = tok0 + 8;
#pragma unroll
        for (int nt2 = 0; nt2 < 8; nt2++) {
            int dc = h * Dq + nt2 * 8 + 2 * t;
            *(float2*)&g_ctx[tok0 * Cq + dc] =
                make_float2(vacc[mt][nt2][0], vacc[mt][nt2][1]);
            *(float2*)&g_ctx[tok1 * Cq + dc] =
                make_float2(vacc[mt][nt2][2], vacc[mt][nt2][3]);
        }
    }
}

// ===========================================================================
extern "C" void kernel_launch(void* const* d_in, const int* in_sizes, int n_in,
                              void* d_out, int out_size)
{
    const float* x      = (const float*)d_in[0];
    const float* w_qkv  = (const float*)d_in[1];
    const float* w_proj = (const float*)d_in[2];
    const float* b_proj = (const float*)d_in[3];

    const size_t out_elems  = (size_t)Mq * Cq;
    const size_t attn_elems = (size_t)BHq * Nq * (size_t)Nq;

    float* outp  = nullptr;
    float* attnp = nullptr;
    if ((size_t)out_size >= out_elems + attn_elems) {
        outp  = (float*)d_out;
        attnp = (float*)d_out + out_elems;
    } else if ((size_t)out_size == attn_elems) {
        attnp = (float*)d_out;
    } else {
        outp = (float*)d_out;
    }

    static const int gsm_bytes = G_SMEM_FLOATS * 4;
    cudaFuncSetAttribute(qkv_gemm_kernel, cudaFuncAttributeMaxDynamicSharedMemorySize,
                         gsm_bytes);
    cudaFuncSetAttribute(proj_gemm_kernel, cudaFuncAttributeMaxDynamicSharedMemorySize,
                         gsm_bytes);

    qkv_gemm_kernel<<<dim3(QKVq / 128, Mq / 128), 256, gsm_bytes>>>(x, w_qkv);

    static const int asm_bytes = A_SMEM_FLOATS * 4;   // 71680
    cudaFuncSetAttribute(attn_kernel, cudaFuncAttributeMaxDynamicSharedMemorySize,
                         asm_bytes);
    attn_kernel<<<dim3(Nq / 256, BHq), 256, asm_bytes>>>(attnp);

    if (outp) {
        proj_gemm_kernel<<<dim3(Cq / 128, Mq / 128), 256, gsm_bytes>>>(w_proj, b_proj, outp);
    }
}